// round 1
// baseline (speedup 1.0000x reference)
#include <cuda_runtime.h>
#include <cuda_bf16.h>

#define DD 16
#define LL 6
#define KK 64

// Scratch (allocation-free): normalized mus in [l][k][d] layout (float4-wise),
// folded alpha constants, and per-layer recurrence weights.
__device__ float4 g_mu[LL * KK * (DD / 4)];
__device__ float  g_c2[LL * KK];
__device__ float  g_wv[LL];

// Constants
#define LOG2E      1.4426950408889634f
#define C1_        (-7.2134752044448169f)   /* -5 * log2(e)      */
#define C2SCALE_   (-14.426950408889634f)   /* -10 * log2(e)     */
#define PI_        3.14159265358979323846f
#define LN2_TENTH  0.069314718055994531f    /* 0.1 * ln(2)       */
#define CLIP_      0.99999994f              /* fp32(1.0 - 1e-7)  */

__global__ void prep_kernel(const float* __restrict__ mus,
                            const float* __restrict__ alphas,
                            const float* __restrict__ ws) {
    int tid = threadIdx.x;
    if (tid < LL) {
        float w = ws[tid];
        g_wv[tid] = expf(-w * w);
    }
    if (tid >= LL * KK) return;
    int l = tid >> 6;
    int k = tid & 63;
    // mus layout: [L, D, K] -> element (l,d,k) at l*D*K + d*K + k
    const float* m = mus + l * DD * KK + k;
    float v[DD];
    float s = 0.f;
#pragma unroll
    for (int d = 0; d < DD; d++) {
        v[d] = m[d * KK];
        s += v[d] * v[d];
    }
    float inv = 1.0f / sqrtf(s);
    float* dst = reinterpret_cast<float*>(&g_mu[tid * 4]);
#pragma unroll
    for (int d = 0; d < DD; d++) dst[d] = v[d] * inv;
    g_c2[tid] = C2SCALE_ * alphas[tid];
}

__device__ __forceinline__ float fast_sqrt(float x) {
    float r;
    asm("sqrt.approx.f32 %0, %1;" : "=f"(r) : "f"(x));
    return r;
}
__device__ __forceinline__ float fast_ex2(float x) {
    float r;
    asm("ex2.approx.f32 %0, %1;" : "=f"(r) : "f"(x));
    return r;
}
__device__ __forceinline__ float fast_lg2(float x) {
    float r;
    asm("lg2.approx.f32 %0, %1;" : "=f"(r) : "f"(x));
    return r;
}

__global__ __launch_bounds__(256) void main_kernel(const float* __restrict__ xs,
                                                   float* __restrict__ out,
                                                   int n_total) {
    __shared__ float4 s_mu[LL * KK * 4];   // 24 KB
    __shared__ float  s_c2[LL * KK];
    __shared__ float  s_wv[LL];

    int tid = threadIdx.x;
    for (int i = tid; i < LL * KK * 4; i += 256) s_mu[i] = g_mu[i];
    for (int i = tid; i < LL * KK; i += 256) s_c2[i] = g_c2[i];
    if (tid < LL) s_wv[tid] = g_wv[tid];
    __syncthreads();

    int n = blockIdx.x * 256 + tid;
    if (n >= n_total) return;

    const float4* xp = reinterpret_cast<const float4*>(xs + (size_t)n * DD);
    float4 x0 = xp[0], x1 = xp[1], x2 = xp[2], x3 = xp[3];

    float F = 0.f;
#pragma unroll
    for (int l = 0; l < LL; l++) {
        float sum = 0.f;
        const int base = l * KK;
#pragma unroll 8
        for (int k = 0; k < KK; k++) {
            int idx = base + k;
            float4 m0 = s_mu[idx * 4 + 0];
            float4 m1 = s_mu[idx * 4 + 1];
            float4 m2 = s_mu[idx * 4 + 2];
            float4 m3 = s_mu[idx * 4 + 3];

            // dot product, two independent accumulator chains for ILP
            float acc0 = x0.x * m0.x;
            float acc1 = x2.x * m2.x;
            acc0 = fmaf(x0.y, m0.y, acc0);
            acc1 = fmaf(x2.y, m2.y, acc1);
            acc0 = fmaf(x0.z, m0.z, acc0);
            acc1 = fmaf(x2.z, m2.z, acc1);
            acc0 = fmaf(x0.w, m0.w, acc0);
            acc1 = fmaf(x2.w, m2.w, acc1);
            acc0 = fmaf(x1.x, m1.x, acc0);
            acc1 = fmaf(x3.x, m3.x, acc1);
            acc0 = fmaf(x1.y, m1.y, acc0);
            acc1 = fmaf(x3.y, m3.y, acc1);
            acc0 = fmaf(x1.z, m1.z, acc0);
            acc1 = fmaf(x3.z, m3.z, acc1);
            acc0 = fmaf(x1.w, m1.w, acc0);
            acc1 = fmaf(x3.w, m3.w, acc1);
            float dot = acc0 + acc1;

            // clip to [-(1-1e-7), 1-1e-7] like the reference
            float t = fminf(fmaxf(dot, -CLIP_), CLIP_);
            float a = fabsf(t);

            // arccos minimax (A&S 4.4.45): acos(a) = sqrt(1-a)*poly(a), |err|<=2e-8
            float p = fmaf(-0.0012624911f, a, 0.0066700901f);
            p = fmaf(p, a, -0.0170881256f);
            p = fmaf(p, a, 0.0308918810f);
            p = fmaf(p, a, -0.0501743046f);
            p = fmaf(p, a, 0.0889789874f);
            p = fmaf(p, a, -0.2145988016f);
            p = fmaf(p, a, 1.5707963050f);
            float dpos = fast_sqrt(1.0f - a) * p;
            float dist = (t < 0.f) ? (PI_ - dpos) : dpos;

            // exp(-(0.5*d^2 + alpha)/0.1) = exp2(C1*d^2 + c2)
            float arg = fmaf(dist * dist, C1_, s_c2[idx]);
            sum += fast_ex2(arg);
        }
        // mincost = 0.1 * ln(sum)   (single-pass LSE: safe, args in [-60, +15])
        float mincost = LN2_TENTH * fast_lg2(sum);
        float w = s_wv[l];
        F = fmaf(w, fmaxf(F, 0.f), (1.0f - w) * mincost);
    }

    // smooth min(F, 0): 0.1 * log(1 + exp(-10F))
    float s = fast_ex2(C2SCALE_ * F);
    out[n] = 0.1f * log1pf(s);
}

extern "C" void kernel_launch(void* const* d_in, const int* in_sizes, int n_in,
                              void* d_out, int out_size) {
    const float* xs     = (const float*)d_in[0];
    const float* mus    = (const float*)d_in[1];
    const float* alphas = (const float*)d_in[2];
    const float* ws     = (const float*)d_in[3];
    float* out = (float*)d_out;

    int n_total = in_sizes[0] / DD;

    prep_kernel<<<1, LL * KK>>>(mus, alphas, ws);
    int blocks = (n_total + 255) / 256;
    main_kernel<<<blocks, 256>>>(xs, out, n_total);
}

// round 2
// speedup vs baseline: 1.0538x; 1.0538x over previous
#include <cuda_runtime.h>
#include <cuda_bf16.h>

#define DD 16
#define LL 6
#define KK 64

typedef unsigned long long u64;

// Scratch: normalized mus in [l][k][d] layout (float4/ulonglong2-friendly),
// folded alpha constants, per-layer recurrence weights.
__device__ float4 g_mu[LL * KK * (DD / 4)];
__device__ float  g_c2[LL * KK];
__device__ float  g_wv[LL];

#define C1_        (-7.2134752044448169f)   /* -5 * log2(e)      */
#define C2SCALE_   (-14.426950408889634f)   /* -10 * log2(e)     */
#define PI_        3.14159265358979323846f
#define LN2_TENTH  0.069314718055994531f    /* 0.1 * ln(2)       */
#define CLIP_      0.99999994f              /* fp32(1.0 - 1e-7)  */

__global__ void prep_kernel(const float* __restrict__ mus,
                            const float* __restrict__ alphas,
                            const float* __restrict__ ws) {
    int tid = threadIdx.x;
    if (tid < LL) {
        float w = ws[tid];
        g_wv[tid] = expf(-w * w);
    }
    if (tid >= LL * KK) return;
    int l = tid >> 6;
    int k = tid & 63;
    // mus layout: [L, D, K] -> element (l,d,k) at l*D*K + d*K + k
    const float* m = mus + l * DD * KK + k;
    float v[DD];
    float s = 0.f;
#pragma unroll
    for (int d = 0; d < DD; d++) {
        v[d] = m[d * KK];
        s += v[d] * v[d];
    }
    float inv = 1.0f / sqrtf(s);
    float* dst = reinterpret_cast<float*>(&g_mu[tid * 4]);
#pragma unroll
    for (int d = 0; d < DD; d++) dst[d] = v[d] * inv;
    g_c2[tid] = C2SCALE_ * alphas[tid];
}

// ---------- fast scalar transcendentals ----------
__device__ __forceinline__ float fast_sqrt(float x) {
    float r; asm("sqrt.approx.f32 %0, %1;" : "=f"(r) : "f"(x)); return r;
}
__device__ __forceinline__ float fast_ex2(float x) {
    float r; asm("ex2.approx.f32 %0, %1;" : "=f"(r) : "f"(x)); return r;
}
__device__ __forceinline__ float fast_lg2(float x) {
    float r; asm("lg2.approx.f32 %0, %1;" : "=f"(r) : "f"(x)); return r;
}

// ---------- packed f32x2 ops (SASS FFMA2/FMUL2/FADD2, PTX-only path) ----------
__device__ __forceinline__ u64 fma2(u64 a, u64 b, u64 c) {
    u64 d; asm("fma.rn.f32x2 %0, %1, %2, %3;" : "=l"(d) : "l"(a), "l"(b), "l"(c)); return d;
}
__device__ __forceinline__ u64 mul2(u64 a, u64 b) {
    u64 d; asm("mul.rn.f32x2 %0, %1, %2;" : "=l"(d) : "l"(a), "l"(b)); return d;
}
__device__ __forceinline__ u64 add2(u64 a, u64 b) {
    u64 d; asm("add.rn.f32x2 %0, %1, %2;" : "=l"(d) : "l"(a), "l"(b)); return d;
}
__device__ __forceinline__ u64 pack2(float lo, float hi) {
    u64 d; asm("mov.b64 %0, {%1, %2};" : "=l"(d) : "f"(lo), "f"(hi)); return d;
}
__device__ __forceinline__ void unpack2(u64 v, float& lo, float& hi) {
    asm("mov.b64 {%0, %1}, %2;" : "=f"(lo), "=f"(hi) : "l"(v));
}

// packed dot of x (8 pairs) with one mu row (4 ulonglong2 = 8 pairs)
__device__ __forceinline__ float dot16(const u64* xp, const ulonglong2* m) {
    u64 a = mul2(xp[0], m[0].x);
    u64 b = mul2(xp[1], m[0].y);
    a = fma2(xp[2], m[1].x, a);
    b = fma2(xp[3], m[1].y, b);
    a = fma2(xp[4], m[2].x, a);
    b = fma2(xp[5], m[2].y, b);
    a = fma2(xp[6], m[3].x, a);
    b = fma2(xp[7], m[3].y, b);
    u64 s = add2(a, b);
    float lo, hi;
    unpack2(s, lo, hi);
    return lo + hi;
}

__global__ __launch_bounds__(256) void main_kernel(const float* __restrict__ xs,
                                                   float* __restrict__ out,
                                                   int n_total) {
    // mu stored as 4 ulonglong2 per (l,k): pairs (d0,d1)(d2,d3)... zero-cost packing
    __shared__ ulonglong2 s_mu[LL * KK * 4];   // 24 KB
    __shared__ float2     s_c2[LL * KK / 2];
    __shared__ float      s_wv[LL];

    int tid = threadIdx.x;
    {
        const ulonglong2* gm = reinterpret_cast<const ulonglong2*>(g_mu);
        for (int i = tid; i < LL * KK * 4; i += 256) s_mu[i] = gm[i];
        const float2* gc = reinterpret_cast<const float2*>(g_c2);
        for (int i = tid; i < LL * KK / 2; i += 256) s_c2[i] = gc[i];
        if (tid < LL) s_wv[tid] = g_wv[tid];
    }
    __syncthreads();

    int n = blockIdx.x * 256 + tid;
    if (n >= n_total) return;

    // x as 8 aligned f32 pairs (natural layout from 128-bit loads)
    u64 xp[8];
    {
        const ulonglong2* xv = reinterpret_cast<const ulonglong2*>(xs + (size_t)n * DD);
        ulonglong2 v0 = xv[0], v1 = xv[1], v2 = xv[2], v3 = xv[3];
        xp[0] = v0.x; xp[1] = v0.y; xp[2] = v1.x; xp[3] = v1.y;
        xp[4] = v2.x; xp[5] = v2.y; xp[6] = v3.x; xp[7] = v3.y;
    }

    // hoisted packed polynomial constants (acos minimax, A&S 4.4.45)
    const u64 P7 = pack2(-0.0012624911f, -0.0012624911f);
    const u64 P6 = pack2( 0.0066700901f,  0.0066700901f);
    const u64 P5 = pack2(-0.0170881256f, -0.0170881256f);
    const u64 P4 = pack2( 0.0308918810f,  0.0308918810f);
    const u64 P3 = pack2(-0.0501743046f, -0.0501743046f);
    const u64 P2 = pack2( 0.0889789874f,  0.0889789874f);
    const u64 P1 = pack2(-0.2145988016f, -0.2145988016f);
    const u64 P0 = pack2( 1.5707963050f,  1.5707963050f);

    float F = 0.f;
#pragma unroll 1
    for (int l = 0; l < LL; l++) {
        float sum0 = 0.f, sum1 = 0.f;
        const ulonglong2* mbase = s_mu + l * KK * 4;
        const float2*     cbase = s_c2 + l * (KK / 2);
#pragma unroll 4
        for (int kp = 0; kp < KK / 2; kp++) {
            const ulonglong2* m0 = mbase + (2 * kp) * 4;
            const ulonglong2* m1 = mbase + (2 * kp + 1) * 4;
            float dot0 = dot16(xp, m0);
            float dot1 = dot16(xp, m1);

            // clip magnitude (clip is symmetric; sign kept in dot for select)
            float a0 = fminf(fabsf(dot0), CLIP_);
            float a1 = fminf(fabsf(dot1), CLIP_);

            // packed polynomial over the k-pair
            u64 pa = pack2(a0, a1);
            u64 p = fma2(P7, pa, P6);
            p = fma2(p, pa, P5);
            p = fma2(p, pa, P4);
            p = fma2(p, pa, P3);
            p = fma2(p, pa, P2);
            p = fma2(p, pa, P1);
            p = fma2(p, pa, P0);
            float p0, p1;
            unpack2(p, p0, p1);

            float s0 = fast_sqrt(1.0f - a0);
            float s1 = fast_sqrt(1.0f - a1);
            float dp0 = s0 * p0;
            float dp1 = s1 * p1;
            float dist0 = (dot0 < 0.f) ? (PI_ - dp0) : dp0;
            float dist1 = (dot1 < 0.f) ? (PI_ - dp1) : dp1;

            float2 c2 = cbase[kp];
            float arg0 = fmaf(dist0 * dist0, C1_, c2.x);
            float arg1 = fmaf(dist1 * dist1, C1_, c2.y);
            sum0 += fast_ex2(arg0);
            sum1 += fast_ex2(arg1);
        }
        float mincost = LN2_TENTH * fast_lg2(sum0 + sum1);
        float w = s_wv[l];
        F = fmaf(w, fmaxf(F, 0.f), (1.0f - w) * mincost);
    }

    // smooth min(F, 0): 0.1 * log(1 + exp(-10F))
    float s = fast_ex2(C2SCALE_ * F);
    out[n] = 0.1f * log1pf(s);
}

extern "C" void kernel_launch(void* const* d_in, const int* in_sizes, int n_in,
                              void* d_out, int out_size) {
    const float* xs     = (const float*)d_in[0];
    const float* mus    = (const float*)d_in[1];
    const float* alphas = (const float*)d_in[2];
    const float* ws     = (const float*)d_in[3];
    float* out = (float*)d_out;

    int n_total = in_sizes[0] / DD;

    prep_kernel<<<1, LL * KK>>>(mus, alphas, ws);
    int blocks = (n_total + 255) / 256;
    main_kernel<<<blocks, 256>>>(xs, out, n_total);
}